// round 2
// baseline (speedup 1.0000x reference)
#include <cuda_runtime.h>

// Problem constants (fixed by the dataset)
#define NN   50000
#define EE   1600000
#define EN   1650000      // EE + NN self loops
#define IND  256
#define HID  256
#define OUTD 48
#define OUT4 12           // OUTD / 4
#define NBS  196          // ceil(NN/256) scan blocks

// ---------------- scratch (device globals; no allocation allowed) ----------
__device__ float     g_relu[NN * HID];    // relu(x@W1+b1)
__device__ float     g_h[NN * OUTD];      // MLP output h
__device__ float     g_p0[NN * OUTD];     // propagation ping
__device__ float     g_p1[NN * OUTD];     // propagation pong
__device__ int       g_deg[NN];
__device__ int       g_scan[NN];
__device__ int       g_bsum[256];
__device__ int       g_boff[256];
__device__ int       g_rowptr[NN + 1];
__device__ int       g_cursor[NN];
__device__ float     g_dinv[NN];
__device__ long long g_edges[EN];         // packed {src:int32 (lo), norm:f32 (hi)}

// ---------------- CSR build -------------------------------------------------
__global__ void k_init_deg() {
    int i = blockIdx.x * blockDim.x + threadIdx.x;
    if (i < NN) g_deg[i] = 1;   // self loop
}

// edge_index arrives as int32 (harness converts int64 -> int32): [2, EE]
__global__ void k_count(const int* __restrict__ ei) {
    int i = blockIdx.x * blockDim.x + threadIdx.x;
    if (i < EE) {
        int d = ei[EE + i];
        if ((unsigned)d < NN) atomicAdd(&g_deg[d], 1);
    }
}

__global__ void k_scan1() {
    __shared__ int s[256];
    int tx = threadIdx.x;
    int i = blockIdx.x * 256 + tx;
    int v = (i < NN) ? g_deg[i] : 0;
    s[tx] = v;
    __syncthreads();
    #pragma unroll
    for (int off = 1; off < 256; off <<= 1) {
        int add = (tx >= off) ? s[tx - off] : 0;
        __syncthreads();
        s[tx] += add;
        __syncthreads();
    }
    if (i < NN) g_scan[i] = s[tx];
    if (tx == 255) g_bsum[blockIdx.x] = s[255];
}

__global__ void k_scan2() {
    __shared__ int s[256];
    int tx = threadIdx.x;
    int v = (tx < NBS) ? g_bsum[tx] : 0;
    s[tx] = v;
    __syncthreads();
    #pragma unroll
    for (int off = 1; off < 256; off <<= 1) {
        int add = (tx >= off) ? s[tx - off] : 0;
        __syncthreads();
        s[tx] += add;
        __syncthreads();
    }
    g_boff[tx] = s[tx] - v;   // exclusive
}

__global__ void k_scan3() {
    int i = blockIdx.x * blockDim.x + threadIdx.x;
    if (i >= NN) return;
    int incl = g_scan[i] + g_boff[i >> 8];
    g_rowptr[i + 1] = incl;
    g_cursor[i] = incl - g_deg[i];           // exclusive start
    g_dinv[i] = rsqrtf((float)g_deg[i]);     // deg >= 1 always
    if (i == 0) g_rowptr[0] = 0;
}

__global__ void k_fill(const int* __restrict__ ei) {
    int i = blockIdx.x * blockDim.x + threadIdx.x;
    if (i >= EN) return;
    int s, d;
    if (i < EE) { s = ei[i]; d = ei[EE + i]; }
    else        { s = i - EE; d = s; }
    if ((unsigned)s >= NN || (unsigned)d >= NN) return;
    float w = g_dinv[s] * g_dinv[d];
    int pos = atomicAdd(&g_cursor[d], 1);
    g_edges[pos] = (long long)(unsigned)s |
                   ((long long)__float_as_uint(w) << 32);
}

// ---------------- GEMM1: g_relu = relu(x @ W1 + b1) -------------------------
// 64x64 tile, 256 threads, 4x4 per thread, fp32.
__global__ void k_gemm1(const float* __restrict__ A, const float* __restrict__ B,
                        const float* __restrict__ bias) {
    __shared__ float As[16][64];   // transposed tile
    __shared__ float Bs[16][64];
    int tid  = threadIdx.x;
    int brow = blockIdx.y * 64;
    int bcol = blockIdx.x * 64;
    int tr = tid >> 4, tc = tid & 15;
    int a_row = tid >> 2;
    int a_k4  = (tid & 3) << 2;
    int b_k   = tid >> 4;
    int b_c4  = (tid & 15) << 2;
    int grow = brow + a_row;
    bool aok = grow < NN;

    float acc[4][4];
    #pragma unroll
    for (int i = 0; i < 4; ++i)
        #pragma unroll
        for (int j = 0; j < 4; ++j) acc[i][j] = 0.f;

    for (int k0 = 0; k0 < IND; k0 += 16) {
        float4 av = aok ? *(const float4*)(A + grow * IND + k0 + a_k4)
                        : make_float4(0.f, 0.f, 0.f, 0.f);
        float4 bv = *(const float4*)(B + (k0 + b_k) * HID + bcol + b_c4);
        As[a_k4 + 0][a_row] = av.x;
        As[a_k4 + 1][a_row] = av.y;
        As[a_k4 + 2][a_row] = av.z;
        As[a_k4 + 3][a_row] = av.w;
        *(float4*)&Bs[b_k][b_c4] = bv;
        __syncthreads();
        #pragma unroll
        for (int k = 0; k < 16; ++k) {
            float4 ar = *(const float4*)&As[k][tr << 2];
            float4 br = *(const float4*)&Bs[k][tc << 2];
            float a_[4] = {ar.x, ar.y, ar.z, ar.w};
            float b_[4] = {br.x, br.y, br.z, br.w};
            #pragma unroll
            for (int i = 0; i < 4; ++i)
                #pragma unroll
                for (int j = 0; j < 4; ++j)
                    acc[i][j] = fmaf(a_[i], b_[j], acc[i][j]);
        }
        __syncthreads();
    }
    float4 bb = *(const float4*)(bias + bcol + (tc << 2));
    float bsv[4] = {bb.x, bb.y, bb.z, bb.w};
    #pragma unroll
    for (int i = 0; i < 4; ++i) {
        int gr = brow + (tr << 2) + i;
        if (gr < NN) {
            float4 o;
            o.x = fmaxf(acc[i][0] + bsv[0], 0.f);
            o.y = fmaxf(acc[i][1] + bsv[1], 0.f);
            o.z = fmaxf(acc[i][2] + bsv[2], 0.f);
            o.w = fmaxf(acc[i][3] + bsv[3], 0.f);
            *(float4*)(g_relu + gr * HID + bcol + (tc << 2)) = o;
        }
    }
}

// ---------------- GEMM2: g_h = g_relu @ W2 + b2 -----------------------------
// 128 rows/block, 256 threads, 4 rows x 6 cols per thread.
__global__ void k_gemm2(const float* __restrict__ W, const float* __restrict__ bias) {
    __shared__ float Ws[64 * 48];      // 12 KB chunk of W2
    __shared__ float As[128 * 68];     // 128 rows x 64 k (stride 68 pad)
    int tid  = threadIdx.x;
    int row0 = blockIdx.x * 128;
    int rg = tid >> 3;    // 0..31 -> rows rg*4..rg*4+3
    int cg = tid & 7;     // cols cg*6..cg*6+5

    float acc[4][6];
    #pragma unroll
    for (int i = 0; i < 4; ++i)
        #pragma unroll
        for (int j = 0; j < 6; ++j) acc[i][j] = 0.f;

    for (int kb = 0; kb < HID; kb += 64) {
        __syncthreads();
        #pragma unroll
        for (int j = 0; j < 12; ++j) {
            int li = tid + j * 256;          // < 3072
            Ws[li] = W[kb * 48 + li];
        }
        #pragma unroll
        for (int j = 0; j < 8; ++j) {
            int li = tid + j * 256;          // float4 index < 2048
            int r = li >> 4; int c4 = (li & 15) << 2;
            int gr = row0 + r;
            float4 v = (gr < NN) ? *(const float4*)(g_relu + gr * HID + kb + c4)
                                 : make_float4(0.f, 0.f, 0.f, 0.f);
            *(float4*)&As[r * 68 + c4] = v;
        }
        __syncthreads();
        #pragma unroll 4
        for (int k = 0; k < 64; ++k) {
            float w[6];
            #pragma unroll
            for (int j = 0; j < 6; ++j) w[j] = Ws[k * 48 + cg * 6 + j];
            #pragma unroll
            for (int i = 0; i < 4; ++i) {
                float a = As[(rg * 4 + i) * 68 + k];
                #pragma unroll
                for (int j = 0; j < 6; ++j) acc[i][j] = fmaf(a, w[j], acc[i][j]);
            }
        }
    }
    #pragma unroll
    for (int i = 0; i < 4; ++i) {
        int gr = row0 + rg * 4 + i;
        if (gr < NN) {
            #pragma unroll
            for (int j = 0; j < 6; ++j)
                g_h[gr * 48 + cg * 6 + j] = acc[i][j] + bias[cg * 6 + j];
        }
    }
}

// ---------------- propagation ----------------------------------------------
__global__ void k_init_hidden(float* __restrict__ out, const float* __restrict__ temp) {
    int i = blockIdx.x * blockDim.x + threadIdx.x;
    if (i >= NN * OUT4) return;
    float g = __ldg(temp);
    float4 v = ((const float4*)g_h)[i];
    ((float4*)out)[i] = make_float4(g * v.x, g * v.y, g * v.z, g * v.w);
}

// One thread per (node, float4 feature chunk): gather-only, no atomics.
__global__ void k_prop(float* __restrict__ out, const float* __restrict__ temp, int k) {
    int t = blockIdx.x * blockDim.x + threadIdx.x;
    int node = t / 12;
    int fx = t - node * 12;
    if (node >= NN) return;
    const float4* cur; float4* nxt;
    if (k == 1)     { cur = (const float4*)g_h;  nxt = (float4*)g_p0; }
    else if (k & 1) { cur = (const float4*)g_p1; nxt = (float4*)g_p0; }
    else            { cur = (const float4*)g_p0; nxt = (float4*)g_p1; }

    int beg = g_rowptr[node], end = g_rowptr[node + 1];
    float4 acc = make_float4(0.f, 0.f, 0.f, 0.f);
    const int2* ed = (const int2*)g_edges;
    for (int p = beg; p < end; ++p) {
        int2 e = ed[p];
        float w = __int_as_float(e.y);
        float4 v = __ldg(&cur[e.x * 12 + fx]);
        acc.x = fmaf(w, v.x, acc.x);
        acc.y = fmaf(w, v.y, acc.y);
        acc.z = fmaf(w, v.z, acc.z);
        acc.w = fmaf(w, v.w, acc.w);
    }
    int o = node * 12 + fx;
    nxt[o] = acc;
    float g = __ldg(temp + k);
    float4 h = ((float4*)out)[o];
    h.x = fmaf(g, acc.x, h.x);
    h.y = fmaf(g, acc.y, h.y);
    h.z = fmaf(g, acc.z, h.z);
    h.w = fmaf(g, acc.w, h.w);
    ((float4*)out)[o] = h;
}

// ---------------- log_softmax (in place on d_out) ---------------------------
__global__ void k_lsm(float* __restrict__ out) {
    int gt = blockIdx.x * blockDim.x + threadIdx.x;
    int row = gt >> 5;
    int lane = gt & 31;
    if (row >= NN) return;
    float* r = out + row * 48;
    float v0 = r[lane];
    float v1 = (lane < 16) ? r[32 + lane] : -3.4e38f;
    float m = fmaxf(v0, v1);
    #pragma unroll
    for (int s = 16; s; s >>= 1) m = fmaxf(m, __shfl_xor_sync(0xffffffffu, m, s));
    float e = expf(v0 - m) + ((lane < 16) ? expf(v1 - m) : 0.f);
    #pragma unroll
    for (int s = 16; s; s >>= 1) e += __shfl_xor_sync(0xffffffffu, e, s);
    float lse = m + logf(e);
    r[lane] = v0 - lse;
    if (lane < 16) r[32 + lane] = v1 - lse;
}

// ---------------- launch ----------------------------------------------------
extern "C" void kernel_launch(void* const* d_in, const int* in_sizes, int n_in,
                              void* d_out, int out_size) {
    const float* x    = (const float*)d_in[0];
    const int*   ei   = (const int*)d_in[1];      // int32 [2, EE]
    const float* W1   = (const float*)d_in[2];
    const float* b1   = (const float*)d_in[3];
    const float* W2   = (const float*)d_in[4];
    const float* b2   = (const float*)d_in[5];
    const float* temp = (const float*)d_in[6];
    float* out = (float*)d_out;
    (void)in_sizes; (void)n_in; (void)out_size;

    // CSR build
    k_init_deg<<<(NN + 255) / 256, 256>>>();
    k_count<<<(EE + 255) / 256, 256>>>(ei);
    k_scan1<<<NBS, 256>>>();
    k_scan2<<<1, 256>>>();
    k_scan3<<<NBS, 256>>>();
    k_fill<<<(EN + 255) / 256, 256>>>(ei);

    // MLP
    dim3 g1(HID / 64, (NN + 63) / 64);
    k_gemm1<<<g1, 256>>>(x, W1, b1);
    k_gemm2<<<(NN + 127) / 128, 256>>>(W2, b2);

    // hidden = temp[0] * h; then 10 propagation steps
    k_init_hidden<<<(NN * OUT4 + 255) / 256, 256>>>(out, temp);
    for (int k = 1; k <= 10; ++k)
        k_prop<<<(NN * 12 + 191) / 192, 192>>>(out, temp, k);

    k_lsm<<<(NN + 7) / 8, 256>>>(out);
}

// round 3
// speedup vs baseline: 1.1770x; 1.1770x over previous
#include <cuda_runtime.h>
#include <cuda_fp16.h>

// Problem constants (fixed by the dataset)
#define NN   50000
#define EE   1600000
#define EN   1650000      // EE + NN self loops
#define IND  256
#define HID  256
#define OUTD 48
#define KHOP 10
#define NBS  196          // ceil(NN/256) scan blocks

// ---------------- scratch (device globals; no allocation allowed) ----------
__device__ float     g_relu[NN * HID];    // relu(x@W1+b1)
__device__ float     g_h[NN * OUTD];      // MLP output h (fp32)
__device__ uint2     g_rf0[NN * 12];      // fp16 r ping (48 halves per node)
__device__ uint2     g_rf1[NN * 12];      // fp16 r pong
__device__ int       g_deg[NN];
__device__ int       g_scan[NN];
__device__ int       g_bsum[256];
__device__ int       g_boff[256];
__device__ int       g_rowptr[NN + 1];
__device__ int       g_cursor[NN];
__device__ float     g_dinv[NN];
__device__ long long g_edges[EN];         // packed {src:int32 (lo), norm:f32 (hi)}

// ---------------- CSR build -------------------------------------------------
__global__ void k_init_deg() {
    int i = blockIdx.x * blockDim.x + threadIdx.x;
    if (i < NN) g_deg[i] = 1;   // self loop
}

__global__ void k_count(const int* __restrict__ ei) {
    int i = blockIdx.x * blockDim.x + threadIdx.x;
    if (i < EE) {
        int d = ei[EE + i];
        if ((unsigned)d < NN) atomicAdd(&g_deg[d], 1);
    }
}

__global__ void k_scan1() {
    __shared__ int s[256];
    int tx = threadIdx.x;
    int i = blockIdx.x * 256 + tx;
    int v = (i < NN) ? g_deg[i] : 0;
    s[tx] = v;
    __syncthreads();
    #pragma unroll
    for (int off = 1; off < 256; off <<= 1) {
        int add = (tx >= off) ? s[tx - off] : 0;
        __syncthreads();
        s[tx] += add;
        __syncthreads();
    }
    if (i < NN) g_scan[i] = s[tx];
    if (tx == 255) g_bsum[blockIdx.x] = s[255];
}

__global__ void k_scan2() {
    __shared__ int s[256];
    int tx = threadIdx.x;
    int v = (tx < NBS) ? g_bsum[tx] : 0;
    s[tx] = v;
    __syncthreads();
    #pragma unroll
    for (int off = 1; off < 256; off <<= 1) {
        int add = (tx >= off) ? s[tx - off] : 0;
        __syncthreads();
        s[tx] += add;
        __syncthreads();
    }
    g_boff[tx] = s[tx] - v;   // exclusive
}

__global__ void k_scan3() {
    int i = blockIdx.x * blockDim.x + threadIdx.x;
    if (i >= NN) return;
    int incl = g_scan[i] + g_boff[i >> 8];
    g_rowptr[i + 1] = incl;
    g_cursor[i] = incl - g_deg[i];           // exclusive start
    g_dinv[i] = rsqrtf((float)g_deg[i]);     // deg >= 1 always
    if (i == 0) g_rowptr[0] = 0;
}

__global__ void k_fill(const int* __restrict__ ei) {
    int i = blockIdx.x * blockDim.x + threadIdx.x;
    if (i >= EN) return;
    int s, d;
    if (i < EE) { s = ei[i]; d = ei[EE + i]; }
    else        { s = i - EE; d = s; }
    if ((unsigned)s >= NN || (unsigned)d >= NN) return;
    float w = g_dinv[s] * g_dinv[d];
    int pos = atomicAdd(&g_cursor[d], 1);
    g_edges[pos] = (long long)(unsigned)s |
                   ((long long)__float_as_uint(w) << 32);
}

// ---------------- GEMM1: g_relu = relu(x @ W1 + b1) -------------------------
// 128x128 tile, 256 threads, 8x8 per thread, register-prefetched loads.
#define KC 16
__global__ void __launch_bounds__(256, 2)
k_gemm1(const float* __restrict__ A, const float* __restrict__ B,
        const float* __restrict__ bias) {
    __shared__ float As[KC][132];   // transposed A tile (k-major)
    __shared__ float Bs[KC][132];
    int tid  = threadIdx.x;
    int brow = blockIdx.y * 128;
    int bcol = blockIdx.x * 128;
    int tr = tid >> 4, tc = tid & 15;

    // A load: row = tid>>1, k-offset = (tid&1)*8 (two float4)
    int arow = tid >> 1;
    int ak   = (tid & 1) << 3;
    int grow = brow + arow;
    bool aok = grow < NN;
    const float* aptr = A + (long)grow * IND + ak;
    // B load: k-row = tid>>4, col-offset = (tid&15)*8
    int bk = tid >> 4;
    int bc = (tid & 15) << 3;
    const float* bptr = B + bk * HID + bcol + bc;

    float4 pa0, pa1, pb0, pb1;
    const float4 z4 = make_float4(0.f, 0.f, 0.f, 0.f);
    pa0 = aok ? *(const float4*)(aptr)     : z4;
    pa1 = aok ? *(const float4*)(aptr + 4) : z4;
    pb0 = *(const float4*)(bptr);
    pb1 = *(const float4*)(bptr + 4);

    float acc[8][8];
    #pragma unroll
    for (int i = 0; i < 8; ++i)
        #pragma unroll
        for (int j = 0; j < 8; ++j) acc[i][j] = 0.f;

    #pragma unroll 1
    for (int c = 0; c < IND / KC; ++c) {
        __syncthreads();
        As[ak + 0][arow] = pa0.x;
        As[ak + 1][arow] = pa0.y;
        As[ak + 2][arow] = pa0.z;
        As[ak + 3][arow] = pa0.w;
        As[ak + 4][arow] = pa1.x;
        As[ak + 5][arow] = pa1.y;
        As[ak + 6][arow] = pa1.z;
        As[ak + 7][arow] = pa1.w;
        *(float4*)&Bs[bk][bc]     = pb0;
        *(float4*)&Bs[bk][bc + 4] = pb1;
        __syncthreads();
        if (c + 1 < IND / KC) {
            const float* ap = aptr + (c + 1) * KC;
            pa0 = aok ? *(const float4*)(ap)     : z4;
            pa1 = aok ? *(const float4*)(ap + 4) : z4;
            const float* bp = bptr + (c + 1) * KC * HID;
            pb0 = *(const float4*)(bp);
            pb1 = *(const float4*)(bp + 4);
        }
        #pragma unroll
        for (int k = 0; k < KC; ++k) {
            float4 a0 = *(const float4*)&As[k][tr << 2];
            float4 a1 = *(const float4*)&As[k][64 + (tr << 2)];
            float4 b0 = *(const float4*)&Bs[k][tc << 2];
            float4 b1 = *(const float4*)&Bs[k][64 + (tc << 2)];
            float av[8] = {a0.x, a0.y, a0.z, a0.w, a1.x, a1.y, a1.z, a1.w};
            float bv[8] = {b0.x, b0.y, b0.z, b0.w, b1.x, b1.y, b1.z, b1.w};
            #pragma unroll
            for (int i = 0; i < 8; ++i)
                #pragma unroll
                for (int j = 0; j < 8; ++j)
                    acc[i][j] = fmaf(av[i], bv[j], acc[i][j]);
        }
    }

    float4 bb0 = *(const float4*)(bias + bcol + (tc << 2));
    float4 bb1 = *(const float4*)(bias + bcol + 64 + (tc << 2));
    float bsv[8] = {bb0.x, bb0.y, bb0.z, bb0.w, bb1.x, bb1.y, bb1.z, bb1.w};
    #pragma unroll
    for (int half = 0; half < 2; ++half) {
        #pragma unroll
        for (int i = 0; i < 4; ++i) {
            int gr = brow + half * 64 + (tr << 2) + i;
            if (gr < NN) {
                float* orow = g_relu + (long)gr * HID + bcol;
                float4 o0, o1;
                o0.x = fmaxf(acc[half * 4 + i][0] + bsv[0], 0.f);
                o0.y = fmaxf(acc[half * 4 + i][1] + bsv[1], 0.f);
                o0.z = fmaxf(acc[half * 4 + i][2] + bsv[2], 0.f);
                o0.w = fmaxf(acc[half * 4 + i][3] + bsv[3], 0.f);
                o1.x = fmaxf(acc[half * 4 + i][4] + bsv[4], 0.f);
                o1.y = fmaxf(acc[half * 4 + i][5] + bsv[5], 0.f);
                o1.z = fmaxf(acc[half * 4 + i][6] + bsv[6], 0.f);
                o1.w = fmaxf(acc[half * 4 + i][7] + bsv[7], 0.f);
                *(float4*)(orow + (tc << 2))      = o0;
                *(float4*)(orow + 64 + (tc << 2)) = o1;
            }
        }
    }
}

// ---------------- GEMM2: g_h = g_relu @ W2 + b2; seed r_K = temp[K]*h -------
__global__ void k_gemm2(const float* __restrict__ W, const float* __restrict__ bias,
                        const float* __restrict__ temp) {
    __shared__ float Ws[64 * 48];
    __shared__ float As[128 * 68];
    int tid  = threadIdx.x;
    int row0 = blockIdx.x * 128;
    int rg = tid >> 3;
    int cg = tid & 7;

    float acc[4][6];
    #pragma unroll
    for (int i = 0; i < 4; ++i)
        #pragma unroll
        for (int j = 0; j < 6; ++j) acc[i][j] = 0.f;

    for (int kb = 0; kb < HID; kb += 64) {
        __syncthreads();
        #pragma unroll
        for (int j = 0; j < 12; ++j) {
            int li = tid + j * 256;
            Ws[li] = W[kb * 48 + li];
        }
        #pragma unroll
        for (int j = 0; j < 8; ++j) {
            int li = tid + j * 256;
            int r = li >> 4; int c4 = (li & 15) << 2;
            int gr = row0 + r;
            float4 v = (gr < NN) ? *(const float4*)(g_relu + (long)gr * HID + kb + c4)
                                 : make_float4(0.f, 0.f, 0.f, 0.f);
            *(float4*)&As[r * 68 + c4] = v;
        }
        __syncthreads();
        #pragma unroll 4
        for (int k = 0; k < 64; ++k) {
            float w[6];
            #pragma unroll
            for (int j = 0; j < 6; ++j) w[j] = Ws[k * 48 + cg * 6 + j];
            #pragma unroll
            for (int i = 0; i < 4; ++i) {
                float a = As[(rg * 4 + i) * 68 + k];
                #pragma unroll
                for (int j = 0; j < 6; ++j) acc[i][j] = fmaf(a, w[j], acc[i][j]);
            }
        }
    }
    float tK = __ldg(temp + KHOP);     // (1-alpha)^K
    __half* rf = (__half*)g_rf0;
    #pragma unroll
    for (int i = 0; i < 4; ++i) {
        int gr = row0 + rg * 4 + i;
        if (gr < NN) {
            #pragma unroll
            for (int j = 0; j < 6; ++j) {
                float v = acc[i][j] + bias[cg * 6 + j];
                g_h[(long)gr * 48 + cg * 6 + j] = v;
                rf[(long)gr * 48 + cg * 6 + j] = __float2half_rn(tK * v);
            }
        }
    }
}

// ---------------- propagation (Horner): r_k = temp[k]*h + H r_{k+1} ---------
// One thread per (node, 4-feature chunk): gather-only, fp16 storage.
__global__ void k_prop(const float* __restrict__ temp, int k, int srcbuf,
                       float* __restrict__ out) {
    int t = blockIdx.x * blockDim.x + threadIdx.x;
    int node = t / 12;
    if (node >= NN) return;
    int fx = t - node * 12;

    const uint2* __restrict__ cur = srcbuf ? g_rf1 : g_rf0;
    uint2*       __restrict__ nxt = srcbuf ? g_rf0 : g_rf1;

    int beg = g_rowptr[node], end = g_rowptr[node + 1];
    float4 acc = make_float4(0.f, 0.f, 0.f, 0.f);
    const int2* ed = (const int2*)g_edges;
    #pragma unroll 4
    for (int p = beg; p < end; ++p) {
        int2 e = ed[p];
        float w = __int_as_float(e.y);
        uint2 v = __ldg(&cur[e.x * 12 + fx]);
        __half2 h0 = *reinterpret_cast<__half2*>(&v.x);
        __half2 h1 = *reinterpret_cast<__half2*>(&v.y);
        float2 f0 = __half22float2(h0);
        float2 f1 = __half22float2(h1);
        acc.x = fmaf(w, f0.x, acc.x);
        acc.y = fmaf(w, f0.y, acc.y);
        acc.z = fmaf(w, f1.x, acc.z);
        acc.w = fmaf(w, f1.y, acc.w);
    }
    float g = __ldg(temp + k);
    float4 hv = *(const float4*)(g_h + (long)node * 48 + fx * 4);
    float4 r;
    r.x = fmaf(g, hv.x, acc.x);
    r.y = fmaf(g, hv.y, acc.y);
    r.z = fmaf(g, hv.z, acc.z);
    r.w = fmaf(g, hv.w, acc.w);
    if (k == 0) {
        *(float4*)(out + (long)node * 48 + fx * 4) = r;
    } else {
        __half2 o0 = __floats2half2_rn(r.x, r.y);
        __half2 o1 = __floats2half2_rn(r.z, r.w);
        uint2 o;
        o.x = *reinterpret_cast<unsigned*>(&o0);
        o.y = *reinterpret_cast<unsigned*>(&o1);
        nxt[node * 12 + fx] = o;
    }
}

// ---------------- log_softmax (in place on d_out) ---------------------------
__global__ void k_lsm(float* __restrict__ out) {
    int gt = blockIdx.x * blockDim.x + threadIdx.x;
    int row = gt >> 5;
    int lane = gt & 31;
    if (row >= NN) return;
    float* r = out + (long)row * 48;
    float v0 = r[lane];
    float v1 = (lane < 16) ? r[32 + lane] : -3.4e38f;
    float m = fmaxf(v0, v1);
    #pragma unroll
    for (int s = 16; s; s >>= 1) m = fmaxf(m, __shfl_xor_sync(0xffffffffu, m, s));
    float e = expf(v0 - m) + ((lane < 16) ? expf(v1 - m) : 0.f);
    #pragma unroll
    for (int s = 16; s; s >>= 1) e += __shfl_xor_sync(0xffffffffu, e, s);
    float lse = m + logf(e);
    r[lane] = v0 - lse;
    if (lane < 16) r[32 + lane] = v1 - lse;
}

// ---------------- launch ----------------------------------------------------
extern "C" void kernel_launch(void* const* d_in, const int* in_sizes, int n_in,
                              void* d_out, int out_size) {
    const float* x    = (const float*)d_in[0];
    const int*   ei   = (const int*)d_in[1];      // int32 [2, EE]
    const float* W1   = (const float*)d_in[2];
    const float* b1   = (const float*)d_in[3];
    const float* W2   = (const float*)d_in[4];
    const float* b2   = (const float*)d_in[5];
    const float* temp = (const float*)d_in[6];
    float* out = (float*)d_out;
    (void)in_sizes; (void)n_in; (void)out_size;

    // CSR build
    k_init_deg<<<(NN + 255) / 256, 256>>>();
    k_count<<<(EE + 255) / 256, 256>>>(ei);
    k_scan1<<<NBS, 256>>>();
    k_scan2<<<1, 256>>>();
    k_scan3<<<NBS, 256>>>();
    k_fill<<<(EN + 255) / 256, 256>>>(ei);

    // MLP (gemm2 epilogue seeds r_K = temp[K]*h into g_rf0)
    dim3 g1((HID + 127) / 128, (NN + 127) / 128);
    k_gemm1<<<g1, 256>>>(x, W1, b1);
    k_gemm2<<<(NN + 127) / 128, 256>>>(W2, b2, temp);

    // Horner propagation: r_k = temp[k]*h + H r_{k+1}, k = K-1 .. 0
    for (int k = KHOP - 1; k >= 0; --k) {
        int s = KHOP - k;                       // step number 1..K
        int srcbuf = (s & 1) ? 0 : 1;           // r_{k+1} location
        k_prop<<<(NN * 12 + 191) / 192, 192>>>(temp, k, srcbuf, out);
    }

    k_lsm<<<(NN + 7) / 8, 256>>>(out);
}